// round 7
// baseline (speedup 1.0000x reference)
#include <cuda_runtime.h>
#include <cstdint>

// Problem constants
#define T_STEPS 512
#define BATCH   8
#define DDIM    512
#define NDIM    64
#define M_ROWS  (T_STEPS * BATCH)   // 4096 rows for the projection GEMM
#define E_COLS  1152                // 512 (k) + 512 (q) + 64 (wx) + 64 (alpha)

// ---------------------------------------------------------------------------
// Scratch (no cudaMalloc allowed) — ~18.1 MB of __device__ globals
// ---------------------------------------------------------------------------
__device__ float g_k[M_ROWS * DDIM];      // k_all   [T*B, D]
__device__ float g_q[M_ROWS * DDIM];      // q_all   [T*B, D]
__device__ float g_wx[M_ROWS * NDIM];     // Wx_all  [T*B, N]
__device__ float g_alpha[M_ROWS * NDIM];  // sigmoid(ax_all) [T*B, N]
__device__ float g_kq[M_ROWS];            // k·q scalar per (t,b)

// ---------------------------------------------------------------------------
// Fast math helpers (exp-based tanh: ~2-ulp MUFU.EX2, safe at +-inf)
// ---------------------------------------------------------------------------
__device__ __forceinline__ float tanh_f(float x) {
    float e = __expf(2.0f * x);
    // e==inf -> __fdividef returns 0 -> tanh=1 (correct limit)
    return 1.0f - __fdividef(2.0f, e + 1.0f);
}
__device__ __forceinline__ float sigmoid_f(float x) {
    float e = __expf(-x);
    return __fdividef(1.0f, 1.0f + e);
}

// DSMEM helpers
__device__ __forceinline__ uint32_t mapa_sh(uint32_t addr, int rank) {
    uint32_t d;
    asm("mapa.shared::cluster.u32 %0, %1, %2;" : "=r"(d) : "r"(addr), "r"(rank));
    return d;
}
__device__ __forceinline__ float2 ld_dsmem_f2(uint32_t addr) {
    float2 v;
    asm volatile("ld.shared::cluster.v2.f32 {%0, %1}, [%2];"
                 : "=f"(v.x), "=f"(v.y) : "r"(addr));
    return v;
}

// ---------------------------------------------------------------------------
// Kernel 1: fused projection GEMM.
// C[m, e] = sum_d x[m,d] * W[e,d], with W selected per 64-wide e-tile:
//   etile 0..7  -> W_k rows  (store g_k)
//   etile 8..15 -> W_q rows  (store g_q)
//   etile 16    -> W_x rows  (store g_wx)
//   etile 17    -> W_alpha   (store sigmoid(. + b_alpha) to g_alpha)
// Tiling: BM=128, BN=64, BK=32, 256 threads, TM=8, TN=4.
// ---------------------------------------------------------------------------
__global__ void __launch_bounds__(256)
proj_gemm_kernel(const float* __restrict__ x,
                 const float* __restrict__ Wk,
                 const float* __restrict__ Wq,
                 const float* __restrict__ Wx,
                 const float* __restrict__ Wa,
                 const float* __restrict__ ba)
{
    __shared__ float As[32][132];  // [k][m], +4 pad
    __shared__ float Bs[32][68];   // [k][e], +4 pad

    const int tid = threadIdx.x;
    const int m0 = blockIdx.x * 128;
    const int etile = blockIdx.y;

    const float* Wp;
    int erow0, mode;
    if (etile < 8)        { Wp = Wk; erow0 = etile * 64;        mode = 0; }
    else if (etile < 16)  { Wp = Wq; erow0 = (etile - 8) * 64;  mode = 1; }
    else if (etile == 16) { Wp = Wx; erow0 = 0;                 mode = 2; }
    else                  { Wp = Wa; erow0 = 0;                 mode = 3; }

    const int tx = tid & 15;   // N dir: 16 * TN(4) = 64
    const int ty = tid >> 4;   // M dir: 16 * TM(8) = 128

    float acc[8][4];
#pragma unroll
    for (int i = 0; i < 8; i++)
#pragma unroll
        for (int j = 0; j < 4; j++) acc[i][j] = 0.0f;

    const int arow = tid >> 3;         // 0..31
    const int acol = (tid & 7) * 4;    // 0..28
    const int brow = tid >> 2;         // 0..63
    const int bcol = (tid & 3) * 8;    // 0,8,16,24

    for (int k0 = 0; k0 < DDIM; k0 += 32) {
        // A tile: 128 x 32, transposed into As[k][m]
#pragma unroll
        for (int p = 0; p < 4; p++) {
            int r = arow + p * 32;
            float4 v = *(const float4*)(x + (size_t)(m0 + r) * DDIM + k0 + acol);
            As[acol + 0][r] = v.x;
            As[acol + 1][r] = v.y;
            As[acol + 2][r] = v.z;
            As[acol + 3][r] = v.w;
        }
        // B tile: 64 x 32, transposed into Bs[k][e]
        {
            const float* wrow = Wp + (size_t)(erow0 + brow) * DDIM + k0 + bcol;
            float4 v0 = *(const float4*)(wrow);
            float4 v1 = *(const float4*)(wrow + 4);
            Bs[bcol + 0][brow] = v0.x;
            Bs[bcol + 1][brow] = v0.y;
            Bs[bcol + 2][brow] = v0.z;
            Bs[bcol + 3][brow] = v0.w;
            Bs[bcol + 4][brow] = v1.x;
            Bs[bcol + 5][brow] = v1.y;
            Bs[bcol + 6][brow] = v1.z;
            Bs[bcol + 7][brow] = v1.w;
        }
        __syncthreads();

#pragma unroll
        for (int kk = 0; kk < 32; kk++) {
            float a[8];
            float4 a0 = *(const float4*)&As[kk][ty * 8];
            float4 a1 = *(const float4*)&As[kk][ty * 8 + 4];
            a[0] = a0.x; a[1] = a0.y; a[2] = a0.z; a[3] = a0.w;
            a[4] = a1.x; a[5] = a1.y; a[6] = a1.z; a[7] = a1.w;
            float4 bv = *(const float4*)&Bs[kk][tx * 4];
            float bj[4] = {bv.x, bv.y, bv.z, bv.w};
#pragma unroll
            for (int i = 0; i < 8; i++)
#pragma unroll
                for (int j = 0; j < 4; j++)
                    acc[i][j] = fmaf(a[i], bj[j], acc[i][j]);
        }
        __syncthreads();
    }

    // Epilogue
#pragma unroll
    for (int i = 0; i < 8; i++) {
        int m = m0 + ty * 8 + i;
#pragma unroll
        for (int j = 0; j < 4; j++) {
            int el = tx * 4 + j;  // 0..63 within this e-tile
            float v = acc[i][j];
            if (mode == 0) {
                g_k[(size_t)m * DDIM + erow0 + el] = v;
            } else if (mode == 1) {
                g_q[(size_t)m * DDIM + erow0 + el] = v;
            } else if (mode == 2) {
                g_wx[(size_t)m * NDIM + el] = v;
            } else {
                g_alpha[(size_t)m * NDIM + el] = sigmoid_f(v + ba[el]);
            }
        }
    }
}

// ---------------------------------------------------------------------------
// Kernel 2: kq[t,b] = sum_d k[t,b,d] * q[t,b,d]  (one warp per row)
// ---------------------------------------------------------------------------
__global__ void __launch_bounds__(256)
kq_kernel()
{
    int warp = threadIdx.x >> 5;
    int lane = threadIdx.x & 31;
    int row = blockIdx.x * 8 + warp;
    const float* kp = g_k + (size_t)row * DDIM;
    const float* qp = g_q + (size_t)row * DDIM;
    float acc = 0.0f;
#pragma unroll
    for (int i = 0; i < DDIM / 32; i++) {
        int idx = i * 32 + lane;
        acc = fmaf(kp[idx], qp[idx], acc);
    }
#pragma unroll
    for (int off = 16; off > 0; off >>= 1)
        acc += __shfl_xor_sync(0xffffffffu, acc, off);
    if (lane == 0) g_kq[row] = acc;
}

// ---------------------------------------------------------------------------
// Kernel 3: the sequential scan.
// Grid: 64 CTAs, clusters of 8 (one cluster per batch, one CTA per 64-wide
// D-chunk). 256 threads/CTA: thread (n = tid>>2, g = tid&3) owns
// S[b, n, rank*64 + g*16 .. +16] in 16 registers.
// One cluster barrier per step; partial (S·k, S·q) exchanged via DSMEM with
// double-buffered slots. y uses the algebraic identity
//   y = tanh(alpha * (S_prev·q) + (1-alpha) * v * (k·q)).
// ---------------------------------------------------------------------------
__global__ void __launch_bounds__(256, 1) __cluster_dims__(8, 1, 1)
scan_kernel(const float* __restrict__ S0,
            const float* __restrict__ Wr,
            const float* __restrict__ bvec,
            float* __restrict__ outY,
            float* __restrict__ outS)
{
    __shared__ float part[2][NDIM][2];  // [buf][n][{pk,pq}]  (this CTA's partials)
    __shared__ float rbuf[NDIM];        // tanh(Sk) broadcast for W_r matvec

    const int tid = threadIdx.x;
    const int n = tid >> 2;
    const int g = tid & 3;
    const int b = blockIdx.x >> 3;
    const int rank = blockIdx.x & 7;
    const int dbase = rank * 64 + g * 16;

    // Persistent registers
    float S[16], Wreg[16], kc[16], qc[16];

    // W_r row slice -> registers (W_r is [N,N] row-major; v[n] = sum_m Wr[n,m] r[m])
#pragma unroll
    for (int j = 0; j < 16; j += 4) {
        float4 v = *(const float4*)(Wr + n * NDIM + g * 16 + j);
        Wreg[j] = v.x; Wreg[j + 1] = v.y; Wreg[j + 2] = v.z; Wreg[j + 3] = v.w;
    }
    const float breg = bvec[n];

    // Load S0 slice and emit it as S output at t=0
    {
        const float* s0p = S0 + ((size_t)b * NDIM + n) * DDIM + dbase;
        float* so = outS + ((size_t)b * NDIM + n) * DDIM + dbase;  // (t=0)
#pragma unroll
        for (int j = 0; j < 16; j += 4) {
            float4 v = *(const float4*)(s0p + j);
            S[j] = v.x; S[j + 1] = v.y; S[j + 2] = v.z; S[j + 3] = v.w;
            *(float4*)(so + j) = v;
        }
    }

    // Preload t = 0 inputs
    float wxc, alc, kqc;
    {
        const float* kp = g_k + (size_t)b * DDIM + dbase;
        const float* qp = g_q + (size_t)b * DDIM + dbase;
#pragma unroll
        for (int j = 0; j < 16; j += 4) {
            float4 vk = *(const float4*)(kp + j);
            float4 vq = *(const float4*)(qp + j);
            kc[j] = vk.x; kc[j + 1] = vk.y; kc[j + 2] = vk.z; kc[j + 3] = vk.w;
            qc[j] = vq.x; qc[j + 1] = vq.y; qc[j + 2] = vq.z; qc[j + 3] = vq.w;
        }
        wxc = g_wx[(size_t)b * NDIM + n];
        alc = g_alpha[(size_t)b * NDIM + n];
        kqc = g_kq[b];
    }

    const uint32_t part_base =
        (uint32_t)__cvta_generic_to_shared(&part[0][0][0]);

    for (int t = 0; t < T_STEPS; t++) {
        const int buf = t & 1;

        // 1) partial reductions over this CTA's 64-wide D chunk
        float pk = 0.0f, pq = 0.0f;
#pragma unroll
        for (int j = 0; j < 16; j++) {
            pk = fmaf(S[j], kc[j], pk);
            pq = fmaf(S[j], qc[j], pq);
        }
        pk += __shfl_xor_sync(0xffffffffu, pk, 1);
        pk += __shfl_xor_sync(0xffffffffu, pk, 2);
        pq += __shfl_xor_sync(0xffffffffu, pq, 1);
        pq += __shfl_xor_sync(0xffffffffu, pq, 2);
        if (g == 0) {
            part[buf][n][0] = pk;
            part[buf][n][1] = pq;
        }

        // 2) arrive (release: makes STS visible), then prefetch t+1 while
        //    the rest of the cluster catches up.
        asm volatile("barrier.cluster.arrive.aligned;" ::: "memory");

        float kn[16], qn[16], wxn, aln, kqn;
        {
            const int tn = (t + 1 < T_STEPS) ? (t + 1) : t;  // clamp (last iter unused)
            const size_t row = (size_t)tn * BATCH + b;
            const float* kp = g_k + row * DDIM + dbase;
            const float* qp = g_q + row * DDIM + dbase;
#pragma unroll
            for (int j = 0; j < 16; j += 4) {
                float4 vk = *(const float4*)(kp + j);
                float4 vq = *(const float4*)(qp + j);
                kn[j] = vk.x; kn[j + 1] = vk.y; kn[j + 2] = vk.z; kn[j + 3] = vk.w;
                qn[j] = vq.x; qn[j + 1] = vq.y; qn[j + 2] = vq.z; qn[j + 3] = vq.w;
            }
            wxn = g_wx[row * NDIM + n];
            aln = g_alpha[row * NDIM + n];
            kqn = g_kq[row];
        }

        asm volatile("barrier.cluster.wait.aligned;" ::: "memory");

        // 3) all-gather: each of the 4 quad threads reads 2 ranks, then
        //    quad shuffle-reduce -> every thread has the full Sk(n), Sq(n).
        uint32_t la = part_base + (uint32_t)((buf * NDIM + n) * 2 * sizeof(float));
        float2 p1 = ld_dsmem_f2(mapa_sh(la, g));
        float2 p2 = ld_dsmem_f2(mapa_sh(la, g + 4));
        float sk = p1.x + p2.x;
        float sq = p1.y + p2.y;
        sk += __shfl_xor_sync(0xffffffffu, sk, 1);
        sk += __shfl_xor_sync(0xffffffffu, sk, 2);
        sq += __shfl_xor_sync(0xffffffffu, sq, 1);
        sq += __shfl_xor_sync(0xffffffffu, sq, 2);

        // 4) retrieved = tanh(Sk); share across n for the W_r matvec
        float rn = tanh_f(sk);
        if (g == 0) rbuf[n] = rn;
        __syncthreads();

        float accv = 0.0f;
        {
            const float* rb = &rbuf[g * 16];
#pragma unroll
            for (int j = 0; j < 16; j++)
                accv = fmaf(Wreg[j], rb[j], accv);
        }
        accv += __shfl_xor_sync(0xffffffffu, accv, 1);
        accv += __shfl_xor_sync(0xffffffffu, accv, 2);

        const float v  = tanh_f(accv + wxc + breg);
        const float al = alc;
        const float c2 = (1.0f - al) * v;

        // 5) state update + store S_{t+1}
#pragma unroll
        for (int j = 0; j < 16; j++)
            S[j] = fmaf(al, S[j], c2 * kc[j]);

        {
            float* sp = outS + (((size_t)(t + 1) * BATCH + b) * NDIM + n) * DDIM + dbase;
#pragma unroll
            for (int j = 0; j < 16; j += 4)
                *(float4*)(sp + j) = make_float4(S[j], S[j + 1], S[j + 2], S[j + 3]);
        }

        // 6) y_t (no second D-reduction needed)
        if (g == 0) {
            float y = tanh_f(fmaf(al, sq, c2 * kqc));
            outY[((size_t)t * BATCH + b) * NDIM + n] = y;
        }

        // 7) rotate prefetched inputs
#pragma unroll
        for (int j = 0; j < 16; j++) { kc[j] = kn[j]; qc[j] = qn[j]; }
        wxc = wxn; alc = aln; kqc = kqn;
    }

    // No CTA may exit while peers can still read its SMEM via DSMEM.
    asm volatile("barrier.cluster.arrive.aligned;" ::: "memory");
    asm volatile("barrier.cluster.wait.aligned;" ::: "memory");
}

// ---------------------------------------------------------------------------
// Launch
// Inputs (metadata order): x, S0, W_k, W_q, W_x, W_r, b, W_alpha, b_alpha
// Output: concat(output [T,B,N], S [T+1,B,N,D]) as float32
// ---------------------------------------------------------------------------
extern "C" void kernel_launch(void* const* d_in, const int* in_sizes, int n_in,
                              void* d_out, int out_size)
{
    const float* x   = (const float*)d_in[0];
    const float* S0  = (const float*)d_in[1];
    const float* Wk  = (const float*)d_in[2];
    const float* Wq  = (const float*)d_in[3];
    const float* Wx  = (const float*)d_in[4];
    const float* Wrm = (const float*)d_in[5];
    const float* bv  = (const float*)d_in[6];
    const float* Wa  = (const float*)d_in[7];
    const float* ba  = (const float*)d_in[8];

    float* outY = (float*)d_out;
    float* outS = outY + (size_t)T_STEPS * BATCH * NDIM;

    dim3 gemm_grid(M_ROWS / 128, E_COLS / 64);  // (32, 18)
    proj_gemm_kernel<<<gemm_grid, 256>>>(x, Wk, Wq, Wx, Wa, ba);
    kq_kernel<<<M_ROWS / 8, 256>>>();
    scan_kernel<<<64, 256>>>(S0, Wrm, bv, outY, outS);
}

// round 8
// speedup vs baseline: 1.4567x; 1.4567x over previous
#include <cuda_runtime.h>
#include <cstdint>

// Problem constants
#define T_STEPS 512
#define BATCH   8
#define DDIM    512
#define NDIM    64
#define M_ROWS  (T_STEPS * BATCH)   // 4096 rows for the projection GEMM
#define E_COLS  1152                // 512 (k) + 512 (q) + 64 (wx) + 64 (alpha)

// ---------------------------------------------------------------------------
// Scratch (no cudaMalloc allowed) — ~18.1 MB of __device__ globals
// ---------------------------------------------------------------------------
__device__ float g_k[M_ROWS * DDIM];      // k_all   [T*B, D]
__device__ float g_q[M_ROWS * DDIM];      // q_all   [T*B, D]
__device__ float g_wx[M_ROWS * NDIM];     // Wx_all  [T*B, N]
__device__ float g_alpha[M_ROWS * NDIM];  // sigmoid(ax_all) [T*B, N]
__device__ float g_kq[M_ROWS];            // k·q scalar per (t,b)

// ---------------------------------------------------------------------------
// Fast math helpers (exp-based tanh: ~2-ulp MUFU.EX2, safe at +-inf)
// ---------------------------------------------------------------------------
__device__ __forceinline__ float tanh_f(float x) {
    float e = __expf(2.0f * x);
    // e==inf -> __fdividef returns 0 -> tanh=1 (correct limit)
    return 1.0f - __fdividef(2.0f, e + 1.0f);
}
__device__ __forceinline__ float sigmoid_f(float x) {
    float e = __expf(-x);
    return __fdividef(1.0f, 1.0f + e);
}

// ---------------------------------------------------------------------------
// Cluster / mbarrier helpers
// ---------------------------------------------------------------------------
__device__ __forceinline__ uint32_t mapa_sh(uint32_t addr, int rank) {
    uint32_t d;
    asm("mapa.shared::cluster.u32 %0, %1, %2;" : "=r"(d) : "r"(addr), "r"(rank));
    return d;
}
__device__ __forceinline__ void mbar_init(uint32_t addr, uint32_t cnt) {
    asm volatile("mbarrier.init.shared.b64 [%0], %1;" :: "r"(addr), "r"(cnt) : "memory");
}
__device__ __forceinline__ void mbar_expect_tx(uint32_t addr, uint32_t bytes) {
    asm volatile("mbarrier.arrive.expect_tx.shared.b64 _, [%0], %1;"
                 :: "r"(addr), "r"(bytes) : "memory");
}
__device__ __forceinline__ void mbar_wait_parity(uint32_t addr, uint32_t parity) {
    asm volatile(
        "{\n\t"
        ".reg .pred P;\n\t"
        "WAIT_%=:\n\t"
        "mbarrier.try_wait.parity.acquire.cluster.shared::cta.b64 P, [%0], %1, 0x989680;\n\t"
        "@!P bra WAIT_%=;\n\t"
        "}"
        :: "r"(addr), "r"(parity) : "memory");
}
// Remote push (8B) with tx-completion signaled on the TARGET CTA's mbarrier.
__device__ __forceinline__ void st_async_b64(uint32_t raddr, unsigned long long val,
                                             uint32_t rmbar) {
    asm volatile("st.async.shared::cluster.mbarrier::complete_tx::bytes.b64 [%0], %1, [%2];"
                 :: "r"(raddr), "l"(val), "r"(rmbar) : "memory");
}
__device__ __forceinline__ unsigned long long pack_f2(float lo, float hi) {
    unsigned long long r;
    asm("mov.b64 %0, {%1, %2};" : "=l"(r) : "f"(lo), "f"(hi));
    return r;
}

// ---------------------------------------------------------------------------
// Kernel 1: fused projection GEMM (unchanged; ~125 us).
// ---------------------------------------------------------------------------
__global__ void __launch_bounds__(256)
proj_gemm_kernel(const float* __restrict__ x,
                 const float* __restrict__ Wk,
                 const float* __restrict__ Wq,
                 const float* __restrict__ Wx,
                 const float* __restrict__ Wa,
                 const float* __restrict__ ba)
{
    __shared__ float As[32][132];  // [k][m], +4 pad
    __shared__ float Bs[32][68];   // [k][e], +4 pad

    const int tid = threadIdx.x;
    const int m0 = blockIdx.x * 128;
    const int etile = blockIdx.y;

    const float* Wp;
    int erow0, mode;
    if (etile < 8)        { Wp = Wk; erow0 = etile * 64;        mode = 0; }
    else if (etile < 16)  { Wp = Wq; erow0 = (etile - 8) * 64;  mode = 1; }
    else if (etile == 16) { Wp = Wx; erow0 = 0;                 mode = 2; }
    else                  { Wp = Wa; erow0 = 0;                 mode = 3; }

    const int tx = tid & 15;   // N dir: 16 * TN(4) = 64
    const int ty = tid >> 4;   // M dir: 16 * TM(8) = 128

    float acc[8][4];
#pragma unroll
    for (int i = 0; i < 8; i++)
#pragma unroll
        for (int j = 0; j < 4; j++) acc[i][j] = 0.0f;

    const int arow = tid >> 3;         // 0..31
    const int acol = (tid & 7) * 4;    // 0..28
    const int brow = tid >> 2;         // 0..63
    const int bcol = (tid & 3) * 8;    // 0,8,16,24

    for (int k0 = 0; k0 < DDIM; k0 += 32) {
#pragma unroll
        for (int p = 0; p < 4; p++) {
            int r = arow + p * 32;
            float4 v = *(const float4*)(x + (size_t)(m0 + r) * DDIM + k0 + acol);
            As[acol + 0][r] = v.x;
            As[acol + 1][r] = v.y;
            As[acol + 2][r] = v.z;
            As[acol + 3][r] = v.w;
        }
        {
            const float* wrow = Wp + (size_t)(erow0 + brow) * DDIM + k0 + bcol;
            float4 v0 = *(const float4*)(wrow);
            float4 v1 = *(const float4*)(wrow + 4);
            Bs[bcol + 0][brow] = v0.x;
            Bs[bcol + 1][brow] = v0.y;
            Bs[bcol + 2][brow] = v0.z;
            Bs[bcol + 3][brow] = v0.w;
            Bs[bcol + 4][brow] = v1.x;
            Bs[bcol + 5][brow] = v1.y;
            Bs[bcol + 6][brow] = v1.z;
            Bs[bcol + 7][brow] = v1.w;
        }
        __syncthreads();

#pragma unroll
        for (int kk = 0; kk < 32; kk++) {
            float a[8];
            float4 a0 = *(const float4*)&As[kk][ty * 8];
            float4 a1 = *(const float4*)&As[kk][ty * 8 + 4];
            a[0] = a0.x; a[1] = a0.y; a[2] = a0.z; a[3] = a0.w;
            a[4] = a1.x; a[5] = a1.y; a[6] = a1.z; a[7] = a1.w;
            float4 bv = *(const float4*)&Bs[kk][tx * 4];
            float bj[4] = {bv.x, bv.y, bv.z, bv.w};
#pragma unroll
            for (int i = 0; i < 8; i++)
#pragma unroll
                for (int j = 0; j < 4; j++)
                    acc[i][j] = fmaf(a[i], bj[j], acc[i][j]);
        }
        __syncthreads();
    }

#pragma unroll
    for (int i = 0; i < 8; i++) {
        int m = m0 + ty * 8 + i;
#pragma unroll
        for (int j = 0; j < 4; j++) {
            int el = tx * 4 + j;
            float v = acc[i][j];
            if (mode == 0) {
                g_k[(size_t)m * DDIM + erow0 + el] = v;
            } else if (mode == 1) {
                g_q[(size_t)m * DDIM + erow0 + el] = v;
            } else if (mode == 2) {
                g_wx[(size_t)m * NDIM + el] = v;
            } else {
                g_alpha[(size_t)m * NDIM + el] = sigmoid_f(v + ba[el]);
            }
        }
    }
}

// ---------------------------------------------------------------------------
// Kernel 2: kq[t,b] = sum_d k[t,b,d] * q[t,b,d]  (one warp per row)
// ---------------------------------------------------------------------------
__global__ void __launch_bounds__(256)
kq_kernel()
{
    int warp = threadIdx.x >> 5;
    int lane = threadIdx.x & 31;
    int row = blockIdx.x * 8 + warp;
    const float* kp = g_k + (size_t)row * DDIM;
    const float* qp = g_q + (size_t)row * DDIM;
    float acc = 0.0f;
#pragma unroll
    for (int i = 0; i < DDIM / 32; i++) {
        int idx = i * 32 + lane;
        acc = fmaf(kp[idx], qp[idx], acc);
    }
#pragma unroll
    for (int off = 16; off > 0; off >>= 1)
        acc += __shfl_xor_sync(0xffffffffu, acc, off);
    if (lane == 0) g_kq[row] = acc;
}

// ---------------------------------------------------------------------------
// Kernel 3: sequential scan — push-based all-to-all.
// Grid: 64 CTAs, clusters of 8 (one cluster per batch, one CTA per 64-wide
// D-chunk). Thread (n = tid>>2, g = tid&3) owns S[b, n, rank*64+g*16 ..+16].
// Per step: each CTA st.async-pushes its (S·k, S·q) partials (64 x float2)
// into all 8 peers' recv[buf][my_rank][*] slots; each CTA waits on a local
// mbarrier with expect_tx = 4096 B. Double-buffered slots + parity (t>>1)&1.
// Safety: a CTA can only send step t+2 after completing its step t+1 gather,
// which requires every receiver to have consumed its step-t buffer.
// ---------------------------------------------------------------------------
__global__ void __launch_bounds__(256, 1) __cluster_dims__(8, 1, 1)
scan_kernel(const float* __restrict__ S0,
            const float* __restrict__ Wr,
            const float* __restrict__ bvec,
            float* __restrict__ outY,
            float* __restrict__ outS)
{
    __shared__ float2 recv[2][8][NDIM];                 // [buf][src_rank][n]
    __shared__ float rbuf[NDIM];                        // tanh(Sk) broadcast
    __shared__ alignas(8) unsigned long long mbar[2];   // one per buffer

    const int tid = threadIdx.x;
    const int n = tid >> 2;
    const int g = tid & 3;
    const int b = blockIdx.x >> 3;
    const int rank = blockIdx.x & 7;
    const int dbase = rank * 64 + g * 16;

    const uint32_t recv_base = (uint32_t)__cvta_generic_to_shared(&recv[0][0][0]);
    const uint32_t mbar_base = (uint32_t)__cvta_generic_to_shared(&mbar[0]);

    // Init mbarriers (arrive count 1: the per-step expect_tx from tid 0)
    if (tid == 0) {
        mbar_init(mbar_base, 1);
        mbar_init(mbar_base + 8, 1);
    }
    __syncthreads();
    // All peers' mbarriers must be initialized before any st.async targets them.
    asm volatile("barrier.cluster.arrive.aligned;" ::: "memory");
    asm volatile("barrier.cluster.wait.aligned;" ::: "memory");

    // Persistent registers
    float S[16], Wreg[16], kc[16], qc[16];

#pragma unroll
    for (int j = 0; j < 16; j += 4) {
        float4 v = *(const float4*)(Wr + n * NDIM + g * 16 + j);
        Wreg[j] = v.x; Wreg[j + 1] = v.y; Wreg[j + 2] = v.z; Wreg[j + 3] = v.w;
    }
    const float breg = bvec[n];

    // Load S0 slice and emit it as S output at t=0
    {
        const float* s0p = S0 + ((size_t)b * NDIM + n) * DDIM + dbase;
        float* so = outS + ((size_t)b * NDIM + n) * DDIM + dbase;
#pragma unroll
        for (int j = 0; j < 16; j += 4) {
            float4 v = *(const float4*)(s0p + j);
            S[j] = v.x; S[j + 1] = v.y; S[j + 2] = v.z; S[j + 3] = v.w;
            *(float4*)(so + j) = v;
        }
    }

    // Preload t = 0 inputs
    float wxc, alc, kqc;
    {
        const float* kp = g_k + (size_t)b * DDIM + dbase;
        const float* qp = g_q + (size_t)b * DDIM + dbase;
#pragma unroll
        for (int j = 0; j < 16; j += 4) {
            float4 vk = *(const float4*)(kp + j);
            float4 vq = *(const float4*)(qp + j);
            kc[j] = vk.x; kc[j + 1] = vk.y; kc[j + 2] = vk.z; kc[j + 3] = vk.w;
            qc[j] = vq.x; qc[j + 1] = vq.y; qc[j + 2] = vq.z; qc[j + 3] = vq.w;
        }
        wxc = g_wx[(size_t)b * NDIM + n];
        alc = g_alpha[(size_t)b * NDIM + n];
        kqc = g_kq[b];
    }

    for (int t = 0; t < T_STEPS; t++) {
        const int buf = t & 1;
        const uint32_t parity = (uint32_t)((t >> 1) & 1);
        const uint32_t lmbar = mbar_base + (uint32_t)(buf * 8);

        // 1) partial reductions over this CTA's 64-wide D chunk
        float pk = 0.0f, pq = 0.0f;
#pragma unroll
        for (int j = 0; j < 16; j++) {
            pk = fmaf(S[j], kc[j], pk);
            pq = fmaf(S[j], qc[j], pq);
        }
        pk += __shfl_xor_sync(0xffffffffu, pk, 1);
        pk += __shfl_xor_sync(0xffffffffu, pk, 2);
        pq += __shfl_xor_sync(0xffffffffu, pq, 1);
        pq += __shfl_xor_sync(0xffffffffu, pq, 2);

        // 2) post expect for THIS step's gather (early tx is legal: negative
        //    tx accounting balances when this lands), then push partials to
        //    every rank's recv[buf][rank][n] slot.
        if (tid == 0) mbar_expect_tx(lmbar, 8u * NDIM * 8u);  // 4096 B
        if (g == 0) {
            unsigned long long val = pack_f2(pk, pq);
            uint32_t ldata = recv_base +
                (uint32_t)(((buf * 8 + rank) * NDIM + n) * sizeof(float2));
#pragma unroll
            for (int r = 0; r < 8; r++) {
                st_async_b64(mapa_sh(ldata, r), val, mapa_sh(lmbar, r));
            }
        }

        // 3) prefetch t+1 inputs while pushes drain
        float kn[16], qn[16], wxn, aln, kqn;
        {
            const int tn = (t + 1 < T_STEPS) ? (t + 1) : t;  // clamp
            const size_t row = (size_t)tn * BATCH + b;
            const float* kp = g_k + row * DDIM + dbase;
            const float* qp = g_q + row * DDIM + dbase;
#pragma unroll
            for (int j = 0; j < 16; j += 4) {
                float4 vk = *(const float4*)(kp + j);
                float4 vq = *(const float4*)(qp + j);
                kn[j] = vk.x; kn[j + 1] = vk.y; kn[j + 2] = vk.z; kn[j + 3] = vk.w;
                qn[j] = vq.x; qn[j + 1] = vq.y; qn[j + 2] = vq.z; qn[j + 3] = vq.w;
            }
            wxn = g_wx[row * NDIM + n];
            aln = g_alpha[row * NDIM + n];
            kqn = g_kq[row];
        }

        // 4) wait for all 8 ranks' partials (tx-complete, acquire)
        mbar_wait_parity(lmbar, parity);

        // 5) sum the 8 rank-partials — quad thread g sums ranks 2g, 2g+1,
        //    then quad shuffle-reduce (all LOCAL shared loads now).
        float2 p1 = recv[buf][2 * g + 0][n];
        float2 p2 = recv[buf][2 * g + 1][n];
        float sk = p1.x + p2.x;
        float sq = p1.y + p2.y;
        sk += __shfl_xor_sync(0xffffffffu, sk, 1);
        sk += __shfl_xor_sync(0xffffffffu, sk, 2);
        sq += __shfl_xor_sync(0xffffffffu, sq, 1);
        sq += __shfl_xor_sync(0xffffffffu, sq, 2);

        // 6) retrieved = tanh(Sk); share across n for the W_r matvec
        float rn = tanh_f(sk);
        if (g == 0) rbuf[n] = rn;
        __syncthreads();

        float accv = 0.0f;
        {
            const float* rb = &rbuf[g * 16];
#pragma unroll
            for (int j = 0; j < 16; j++)
                accv = fmaf(Wreg[j], rb[j], accv);
        }
        accv += __shfl_xor_sync(0xffffffffu, accv, 1);
        accv += __shfl_xor_sync(0xffffffffu, accv, 2);

        const float v  = tanh_f(accv + wxc + breg);
        const float al = alc;
        const float c2 = (1.0f - al) * v;

        // 7) state update + store S_{t+1}
#pragma unroll
        for (int j = 0; j < 16; j++)
            S[j] = fmaf(al, S[j], c2 * kc[j]);

        {
            float* sp = outS + (((size_t)(t + 1) * BATCH + b) * NDIM + n) * DDIM + dbase;
#pragma unroll
            for (int j = 0; j < 16; j += 4)
                *(float4*)(sp + j) = make_float4(S[j], S[j + 1], S[j + 2], S[j + 3]);
        }

        // 8) y_t = tanh(alpha*(S_prev.q) + (1-alpha)*v*(k.q))
        if (g == 0) {
            float y = tanh_f(fmaf(al, sq, c2 * kqc));
            outY[((size_t)t * BATCH + b) * NDIM + n] = y;
        }

        // 9) rotate prefetched inputs
#pragma unroll
        for (int j = 0; j < 16; j++) { kc[j] = kn[j]; qc[j] = qn[j]; }
        wxc = wxn; alc = aln; kqc = kqn;
    }

    // __syncthreads so every thread's final wait has completed before any
    // thread reaches the exit sync; no CTA exits while peers could still
    // touch its SMEM.
    __syncthreads();
    asm volatile("barrier.cluster.arrive.aligned;" ::: "memory");
    asm volatile("barrier.cluster.wait.aligned;" ::: "memory");
}

// ---------------------------------------------------------------------------
// Launch
// Inputs (metadata order): x, S0, W_k, W_q, W_x, W_r, b, W_alpha, b_alpha
// Output: concat(output [T,B,N], S [T+1,B,N,D]) as float32
// ---------------------------------------------------------------------------
extern "C" void kernel_launch(void* const* d_in, const int* in_sizes, int n_in,
                              void* d_out, int out_size)
{
    const float* x   = (const float*)d_in[0];
    const float* S0  = (const float*)d_in[1];
    const float* Wk  = (const float*)d_in[2];
    const float* Wq  = (const float*)d_in[3];
    const float* Wx  = (const float*)d_in[4];
    const float* Wrm = (const float*)d_in[5];
    const float* bv  = (const float*)d_in[6];
    const float* Wa  = (const float*)d_in[7];
    const float* ba  = (const float*)d_in[8];

    float* outY = (float*)d_out;
    float* outS = outY + (size_t)T_STEPS * BATCH * NDIM;

    dim3 gemm_grid(M_ROWS / 128, E_COLS / 64);  // (32, 18)
    proj_gemm_kernel<<<gemm_grid, 256>>>(x, Wk, Wq, Wx, Wa, ba);
    kq_kernel<<<M_ROWS / 8, 256>>>();
    scan_kernel<<<64, 256>>>(S0, Wrm, bv, outY, outS);
}

// round 11
// speedup vs baseline: 1.5418x; 1.0584x over previous
#include <cuda_runtime.h>
#include <cstdint>

// Problem constants
#define T_STEPS 512
#define BATCH   8
#define DDIM    512
#define NDIM    64
#define M_ROWS  (T_STEPS * BATCH)   // 4096 rows for the projection GEMM
#define E_COLS  1152                // 512 (k) + 512 (q) + 64 (wx) + 64 (alpha)

typedef unsigned long long u64;

// ---------------------------------------------------------------------------
// Scratch (no cudaMalloc allowed)
// ---------------------------------------------------------------------------
__device__ float g_k[M_ROWS * DDIM];      // k_all   [T*B, D]
__device__ float g_q[M_ROWS * DDIM];      // q_all   [T*B, D]
__device__ float g_wx[M_ROWS * NDIM];     // Wx_all  [T*B, N]
__device__ float g_alpha[M_ROWS * NDIM];  // sigmoid(ax_all) [T*B, N]
__device__ float g_kq[M_ROWS];            // k_t . q_t
__device__ float g_kk2[M_ROWS];           // k_{t-1} . k_t   (0 at t=0)
__device__ float g_kqp[M_ROWS];           // k_{t-1} . q_t   (0 at t=0)

// ---------------------------------------------------------------------------
// Fast math helpers
// ---------------------------------------------------------------------------
__device__ __forceinline__ float tanh_f(float x) {
    float e = __expf(2.0f * x);
    return 1.0f - __fdividef(2.0f, e + 1.0f);
}
__device__ __forceinline__ float sigmoid_f(float x) {
    float e = __expf(-x);
    return __fdividef(1.0f, 1.0f + e);
}

// ---------------------------------------------------------------------------
// Cluster / mbarrier helpers
// ---------------------------------------------------------------------------
__device__ __forceinline__ uint32_t mapa_sh(uint32_t addr, int rank) {
    uint32_t d;
    asm("mapa.shared::cluster.u32 %0, %1, %2;" : "=r"(d) : "r"(addr), "r"(rank));
    return d;
}
__device__ __forceinline__ void mbar_init(uint32_t addr, uint32_t cnt) {
    asm volatile("mbarrier.init.shared.b64 [%0], %1;" :: "r"(addr), "r"(cnt) : "memory");
}
__device__ __forceinline__ void mbar_expect_tx(uint32_t addr, uint32_t bytes) {
    asm volatile("mbarrier.arrive.expect_tx.shared.b64 _, [%0], %1;"
                 :: "r"(addr), "r"(bytes) : "memory");
}
__device__ __forceinline__ void mbar_wait_parity(uint32_t addr, uint32_t parity) {
    asm volatile(
        "{\n\t"
        ".reg .pred P;\n\t"
        "WAIT_%=:\n\t"
        "mbarrier.try_wait.parity.acquire.cluster.shared::cta.b64 P, [%0], %1, 0x989680;\n\t"
        "@!P bra WAIT_%=;\n\t"
        "}"
        :: "r"(addr), "r"(parity) : "memory");
}
__device__ __forceinline__ void st_async_b64(uint32_t raddr, u64 val, uint32_t rmbar) {
    asm volatile("st.async.shared::cluster.mbarrier::complete_tx::bytes.b64 [%0], %1, [%2];"
                 :: "r"(raddr), "l"(val), "r"(rmbar) : "memory");
}
__device__ __forceinline__ u64 pack_f2(float lo, float hi) {
    u64 r;
    asm("mov.b64 %0, {%1, %2};" : "=l"(r) : "f"(lo), "f"(hi));
    return r;
}

// ---------------------------------------------------------------------------
// Kernel 1: fused projection GEMM (unchanged; ~125 us)
// ---------------------------------------------------------------------------
__global__ void __launch_bounds__(256)
proj_gemm_kernel(const float* __restrict__ x,
                 const float* __restrict__ Wk,
                 const float* __restrict__ Wq,
                 const float* __restrict__ Wx,
                 const float* __restrict__ Wa,
                 const float* __restrict__ ba)
{
    __shared__ float As[32][132];
    __shared__ float Bs[32][68];

    const int tid = threadIdx.x;
    const int m0 = blockIdx.x * 128;
    const int etile = blockIdx.y;

    const float* Wp;
    int erow0, mode;
    if (etile < 8)        { Wp = Wk; erow0 = etile * 64;        mode = 0; }
    else if (etile < 16)  { Wp = Wq; erow0 = (etile - 8) * 64;  mode = 1; }
    else if (etile == 16) { Wp = Wx; erow0 = 0;                 mode = 2; }
    else                  { Wp = Wa; erow0 = 0;                 mode = 3; }

    const int tx = tid & 15;
    const int ty = tid >> 4;

    float acc[8][4];
#pragma unroll
    for (int i = 0; i < 8; i++)
#pragma unroll
        for (int j = 0; j < 4; j++) acc[i][j] = 0.0f;

    const int arow = tid >> 3;
    const int acol = (tid & 7) * 4;
    const int brow = tid >> 2;
    const int bcol = (tid & 3) * 8;

    for (int k0 = 0; k0 < DDIM; k0 += 32) {
#pragma unroll
        for (int p = 0; p < 4; p++) {
            int r = arow + p * 32;
            float4 v = *(const float4*)(x + (size_t)(m0 + r) * DDIM + k0 + acol);
            As[acol + 0][r] = v.x;
            As[acol + 1][r] = v.y;
            As[acol + 2][r] = v.z;
            As[acol + 3][r] = v.w;
        }
        {
            const float* wrow = Wp + (size_t)(erow0 + brow) * DDIM + k0 + bcol;
            float4 v0 = *(const float4*)(wrow);
            float4 v1 = *(const float4*)(wrow + 4);
            Bs[bcol + 0][brow] = v0.x;
            Bs[bcol + 1][brow] = v0.y;
            Bs[bcol + 2][brow] = v0.z;
            Bs[bcol + 3][brow] = v0.w;
            Bs[bcol + 4][brow] = v1.x;
            Bs[bcol + 5][brow] = v1.y;
            Bs[bcol + 6][brow] = v1.z;
            Bs[bcol + 7][brow] = v1.w;
        }
        __syncthreads();

#pragma unroll
        for (int kk = 0; kk < 32; kk++) {
            float a[8];
            float4 a0 = *(const float4*)&As[kk][ty * 8];
            float4 a1 = *(const float4*)&As[kk][ty * 8 + 4];
            a[0] = a0.x; a[1] = a0.y; a[2] = a0.z; a[3] = a0.w;
            a[4] = a1.x; a[5] = a1.y; a[6] = a1.z; a[7] = a1.w;
            float4 bv = *(const float4*)&Bs[kk][tx * 4];
            float bj[4] = {bv.x, bv.y, bv.z, bv.w};
#pragma unroll
            for (int i = 0; i < 8; i++)
#pragma unroll
                for (int j = 0; j < 4; j++)
                    acc[i][j] = fmaf(a[i], bj[j], acc[i][j]);
        }
        __syncthreads();
    }

#pragma unroll
    for (int i = 0; i < 8; i++) {
        int m = m0 + ty * 8 + i;
#pragma unroll
        for (int j = 0; j < 4; j++) {
            int el = tx * 4 + j;
            float v = acc[i][j];
            if (mode == 0) {
                g_k[(size_t)m * DDIM + erow0 + el] = v;
            } else if (mode == 1) {
                g_q[(size_t)m * DDIM + erow0 + el] = v;
            } else if (mode == 2) {
                g_wx[(size_t)m * NDIM + el] = v;
            } else {
                g_alpha[(size_t)m * NDIM + el] = sigmoid_f(v + ba[el]);
            }
        }
    }
}

// ---------------------------------------------------------------------------
// Kernel 2: per-(t,b) scalars: kq = k_t.q_t, kk2 = k_{t-1}.k_t, kqp = k_{t-1}.q_t
// One warp per row.
// ---------------------------------------------------------------------------
__global__ void __launch_bounds__(256)
kq_kernel()
{
    int warp = threadIdx.x >> 5;
    int lane = threadIdx.x & 31;
    int row = blockIdx.x * 8 + warp;
    const bool has_prev = (row >= BATCH);
    const int prow = has_prev ? (row - BATCH) : row;
    const float* kp = g_k + (size_t)row * DDIM;
    const float* qp = g_q + (size_t)row * DDIM;
    const float* pp = g_k + (size_t)prow * DDIM;
    float akq = 0.0f, akk = 0.0f, akqp = 0.0f;
#pragma unroll
    for (int i = 0; i < DDIM / 32; i++) {
        int idx = i * 32 + lane;
        float kv = kp[idx], qv = qp[idx], pv = pp[idx];
        akq  = fmaf(kv, qv, akq);
        akk  = fmaf(pv, kv, akk);
        akqp = fmaf(pv, qv, akqp);
    }
#pragma unroll
    for (int off = 16; off > 0; off >>= 1) {
        akq  += __shfl_xor_sync(0xffffffffu, akq,  off);
        akk  += __shfl_xor_sync(0xffffffffu, akk,  off);
        akqp += __shfl_xor_sync(0xffffffffu, akqp, off);
    }
    if (lane == 0) {
        g_kq[row]  = akq;
        g_kk2[row] = has_prev ? akk  : 0.0f;
        g_kqp[row] = has_prev ? akqp : 0.0f;
    }
}

// ---------------------------------------------------------------------------
// Kernel 3: pipelined sequential scan.
// At iteration t each CTA pushes partials of G_{t+1} = S_{t-1}.k_{t+1}
// (and S_{t-1}.q_{t+1}) BEFORE consuming the gather for step t, so the DSMEM
// round trip overlaps a full iteration of compute. Consumer reconstructs:
//   Sk_t = a_{t-1} * sum(G_t) + c2_{t-1} * (k_{t-1}.k_t)
//   Sq_t = a_{t-1} * sum(Gq_t) + c2_{t-1} * (k_{t-1}.q_t)
// 4 receive buffers (mod-4), parity (t>>2)&1; rbuf double-buffered.
// ---------------------------------------------------------------------------
__global__ void __launch_bounds__(256, 1) __cluster_dims__(8, 1, 1)
scan_kernel(const float* __restrict__ S0,
            const float* __restrict__ Wr,
            const float* __restrict__ bvec,
            float* __restrict__ outY,
            float* __restrict__ outS)
{
    __shared__ float2 recv[4][8][NDIM];               // [buf][src_rank][n]
    __shared__ float rbuf[2][NDIM];                   // tanh(Sk), double-buffered
    __shared__ alignas(8) u64 mbar[4];

    const int tid = threadIdx.x;
    const int n = tid >> 2;
    const int g = tid & 3;
    const int b = blockIdx.x >> 3;
    const int rank = blockIdx.x & 7;
    const int dbase = rank * 64 + g * 16;

    const uint32_t recv_base = (uint32_t)__cvta_generic_to_shared(&recv[0][0][0]);
    const uint32_t mbar_base = (uint32_t)__cvta_generic_to_shared(&mbar[0]);

    if (tid == 0) {
#pragma unroll
        for (int s = 0; s < 4; s++) mbar_init(mbar_base + s * 8, 1);
#pragma unroll
        for (int s = 0; s < 4; s++) mbar_expect_tx(mbar_base + s * 8, 8u * NDIM * 8u);
    }
    __syncthreads();
    // All peers' mbarriers + expects must exist before any st.async arrives.
    asm volatile("barrier.cluster.arrive.aligned;" ::: "memory");
    asm volatile("barrier.cluster.wait.aligned;" ::: "memory");

    // Persistent registers
    float S[16], Wreg[16], kc[16], kp1[16], qp1[16], kn[16], qn[16];

#pragma unroll
    for (int j = 0; j < 16; j += 4) {
        float4 v = *(const float4*)(Wr + n * NDIM + g * 16 + j);
        Wreg[j] = v.x; Wreg[j + 1] = v.y; Wreg[j + 2] = v.z; Wreg[j + 3] = v.w;
    }
    const float breg = bvec[n];

    // S0 slice; emit as S output at index 0
    {
        const float* s0p = S0 + ((size_t)b * NDIM + n) * DDIM + dbase;
        float* so = outS + ((size_t)b * NDIM + n) * DDIM + dbase;
#pragma unroll
        for (int j = 0; j < 16; j += 4) {
            float4 v = *(const float4*)(s0p + j);
            S[j] = v.x; S[j + 1] = v.y; S[j + 2] = v.z; S[j + 3] = v.w;
            *(float4*)(so + j) = v;
        }
    }

    // k_0 -> kc; q_0 -> qp1 (temporarily, for the G_0 pre-push)
    {
        const float* kp = g_k + (size_t)b * DDIM + dbase;
        const float* qp = g_q + (size_t)b * DDIM + dbase;
#pragma unroll
        for (int j = 0; j < 16; j += 4) {
            float4 vk = *(const float4*)(kp + j);
            float4 vq = *(const float4*)(qp + j);
            kc[j] = vk.x; kc[j + 1] = vk.y; kc[j + 2] = vk.z; kc[j + 3] = vk.w;
            qp1[j] = vq.x; qp1[j + 1] = vq.y; qp1[j + 2] = vq.z; qp1[j + 3] = vq.w;
        }
    }

    // Pre-push G_0 = (S0 . k_0, S0 . q_0) into buf 0
    {
        float pk = 0.0f, pq = 0.0f;
#pragma unroll
        for (int j = 0; j < 16; j++) {
            pk = fmaf(S[j], kc[j], pk);
            pq = fmaf(S[j], qp1[j], pq);
        }
        pk += __shfl_xor_sync(0xffffffffu, pk, 1);
        pk += __shfl_xor_sync(0xffffffffu, pk, 2);
        pq += __shfl_xor_sync(0xffffffffu, pq, 1);
        pq += __shfl_xor_sync(0xffffffffu, pq, 2);
        u64 val = pack_f2(pk, pq);
        uint32_t ldata = recv_base + (uint32_t)(((0 * 8 + rank) * NDIM + n) * sizeof(float2));
        uint32_t lmb = mbar_base + 0;
        st_async_b64(mapa_sh(ldata, 2 * g + 0), val, mapa_sh(lmb, 2 * g + 0));
        st_async_b64(mapa_sh(ldata, 2 * g + 1), val, mapa_sh(lmb, 2 * g + 1));
    }

    // k_1 / q_1 -> kp1/qp1
    {
        const size_t row1 = (size_t)BATCH + b;
        const float* kp = g_k + row1 * DDIM + dbase;
        const float* qp = g_q + row1 * DDIM + dbase;
#pragma unroll
        for (int j = 0; j < 16; j += 4) {
            float4 vk = *(const float4*)(kp + j);
            float4 vq = *(const float4*)(qp + j);
            kp1[j] = vk.x; kp1[j + 1] = vk.y; kp1[j + 2] = vk.z; kp1[j + 3] = vk.w;
            qp1[j] = vq.x; qp1[j + 1] = vq.y; qp1[j + 2] = vq.z; qp1[j + 3] = vq.w;
        }
    }

    // Scalars for t=0
    float alc, wxc, kqc, kk2c, kqpc;
    {
        const size_t row0 = (size_t)b;
        alc  = g_alpha[row0 * NDIM + n];
        wxc  = g_wx[row0 * NDIM + n];
        kqc  = g_kq[row0];
        kk2c = g_kk2[row0];   // = 0
        kqpc = g_kqp[row0];   // = 0
    }

    float a_prev = 1.0f, c2_prev = 0.0f;

    for (int t = 0; t < T_STEPS; t++) {
        // 1) compute + push G_{t+1} partials from S (= S_{t-1}), k_{t+1}, q_{t+1}
        {
            float pk = 0.0f, pq = 0.0f;
#pragma unroll
            for (int j = 0; j < 16; j++) {
                pk = fmaf(S[j], kp1[j], pk);
                pq = fmaf(S[j], qp1[j], pq);
            }
            pk += __shfl_xor_sync(0xffffffffu, pk, 1);
            pk += __shfl_xor_sync(0xffffffffu, pk, 2);
            pq += __shfl_xor_sync(0xffffffffu, pq, 1);
            pq += __shfl_xor_sync(0xffffffffu, pq, 2);
            if (t + 1 < T_STEPS) {
                const int pbuf = (t + 1) & 3;
                u64 val = pack_f2(pk, pq);
                uint32_t ldata = recv_base +
                    (uint32_t)(((pbuf * 8 + rank) * NDIM + n) * sizeof(float2));
                uint32_t lmb = mbar_base + (uint32_t)(pbuf * 8);
                st_async_b64(mapa_sh(ldata, 2 * g + 0), val, mapa_sh(lmb, 2 * g + 0));
                st_async_b64(mapa_sh(ldata, 2 * g + 1), val, mapa_sh(lmb, 2 * g + 1));
            }
        }

        // 2) prefetch k/q for t+2 and scalars for t+1 (clamped)
        float wxn, aln, kqn, kk2n, kqpn;
        {
            const int t2 = (t + 2 < T_STEPS) ? (t + 2) : (T_STEPS - 1);
            const size_t row2 = (size_t)t2 * BATCH + b;
            const float* kp = g_k + row2 * DDIM + dbase;
            const float* qp = g_q + row2 * DDIM + dbase;
#pragma unroll
            for (int j = 0; j < 16; j += 4) {
                float4 vk = *(const float4*)(kp + j);
                float4 vq = *(const float4*)(qp + j);
                kn[j] = vk.x; kn[j + 1] = vk.y; kn[j + 2] = vk.z; kn[j + 3] = vk.w;
                qn[j] = vq.x; qn[j + 1] = vq.y; qn[j + 2] = vq.z; qn[j + 3] = vq.w;
            }
            const int t1 = (t + 1 < T_STEPS) ? (t + 1) : (T_STEPS - 1);
            const size_t row1 = (size_t)t1 * BATCH + b;
            aln  = g_alpha[row1 * NDIM + n];
            wxn  = g_wx[row1 * NDIM + n];
            kqn  = g_kq[row1];
            kk2n = g_kk2[row1];
            kqpn = g_kqp[row1];
        }

        // 3) wait for step t's gather; re-arm this mbarrier for step t+4
        const int wbuf = t & 3;
        const uint32_t parity = (uint32_t)((t >> 2) & 1);
        mbar_wait_parity(mbar_base + (uint32_t)(wbuf * 8), parity);
        if (tid == 0) mbar_expect_tx(mbar_base + (uint32_t)(wbuf * 8), 8u * NDIM * 8u);

        // 4) sum 8 rank-partials + one-step correction
        float2 p1 = recv[wbuf][2 * g + 0][n];
        float2 p2 = recv[wbuf][2 * g + 1][n];
        float skG = p1.x + p2.x;
        float sqG = p1.y + p2.y;
        skG += __shfl_xor_sync(0xffffffffu, skG, 1);
        skG += __shfl_xor_sync(0xffffffffu, skG, 2);
        sqG += __shfl_xor_sync(0xffffffffu, sqG, 1);
        sqG += __shfl_xor_sync(0xffffffffu, sqG, 2);
        const float sk = fmaf(a_prev, skG, c2_prev * kk2c);
        const float sq = fmaf(a_prev, sqG, c2_prev * kqpc);

        // 5) retrieved = tanh(Sk); broadcast; W_r matvec
        const int rb = t & 1;
        float rn = tanh_f(sk);
        if (g == 0) rbuf[rb][n] = rn;
        __syncthreads();

        float accv = 0.0f;
        {
            const float* rp = &rbuf[rb][g * 16];
#pragma unroll
            for (int j = 0; j < 16; j++)
                accv = fmaf(Wreg[j], rp[j], accv);
        }
        accv += __shfl_xor_sync(0xffffffffu, accv, 1);
        accv += __shfl_xor_sync(0xffffffffu, accv, 2);

        const float v  = tanh_f(accv + wxc + breg);
        const float al = alc;
        const float c2 = (1.0f - al) * v;

        // 6) state update + store S_{t+1}
#pragma unroll
        for (int j = 0; j < 16; j++)
            S[j] = fmaf(al, S[j], c2 * kc[j]);
        {
            float* sp = outS + (((size_t)(t + 1) * BATCH + b) * NDIM + n) * DDIM + dbase;
#pragma unroll
            for (int j = 0; j < 16; j += 4)
                *(float4*)(sp + j) = make_float4(S[j], S[j + 1], S[j + 2], S[j + 3]);
        }

        // 7) y_t = tanh(al*Sq_t + c2*(k_t.q_t))
        if (g == 0) {
            float y = tanh_f(fmaf(al, sq, c2 * kqc));
            outY[((size_t)t * BATCH + b) * NDIM + n] = y;
        }

        // 8) rotate pipeline registers / scalars
        a_prev = al; c2_prev = c2;
#pragma unroll
        for (int j = 0; j < 16; j++) { kc[j] = kp1[j]; kp1[j] = kn[j]; qp1[j] = qn[j]; }
        alc = aln; wxc = wxn; kqc = kqn; kk2c = kk2n; kqpc = kqpn;
    }

    __syncthreads();
    asm volatile("barrier.cluster.arrive.aligned;" ::: "memory");
    asm volatile("barrier.cluster.wait.aligned;" ::: "memory");
}

// ---------------------------------------------------------------------------
// Launch
// Inputs (metadata order): x, S0, W_k, W_q, W_x, W_r, b, W_alpha, b_alpha
// Output: concat(output [T,B,N], S [T+1,B,N,D]) as float32
// ---------------------------------------------------------------------------
extern "C" void kernel_launch(void* const* d_in, const int* in_sizes, int n_in,
                              void* d_out, int out_size)
{
    const float* x   = (const float*)d_in[0];
    const float* S0  = (const float*)d_in[1];
    const float* Wk  = (const float*)d_in[2];
    const float* Wq  = (const float*)d_in[3];
    const float* Wx  = (const float*)d_in[4];
    const float* Wrm = (const float*)d_in[5];
    const float* bv  = (const float*)d_in[6];
    const float* Wa  = (const float*)d_in[7];
    const float* ba  = (const float*)d_in[8];

    float* outY = (float*)d_out;
    float* outS = outY + (size_t)T_STEPS * BATCH * NDIM;

    dim3 gemm_grid(M_ROWS / 128, E_COLS / 64);  // (32, 18)
    proj_gemm_kernel<<<gemm_grid, 256>>>(x, Wk, Wq, Wx, Wa, ba);
    kq_kernel<<<M_ROWS / 8, 256>>>();
    scan_kernel<<<64, 256>>>(S0, Wrm, bv, outY, outS);
}